// round 7
// baseline (speedup 1.0000x reference)
#include <cuda_runtime.h>
#include <cstdint>

#define N_NODES 200000
#define F_IN    128
#define H_DIM   64
#define C_OUT   40
#define MAXDEG  5
#define NBUCKET 6
#define NUM_LAYERS 2
#define E_MAX   3400000

#define SCAN_ELEMS 1024
#define NUM_SCAN_BLOCKS ((N_NODES + SCAN_ELEMS - 1) / SCAN_ELEMS)   // 196

// ---------------- scratch (__device__ globals: allocation-free rule) --------
__device__ float g_h  [(size_t)N_NODES * H_DIM];   // layer ping
__device__ float g_x1 [(size_t)N_NODES * H_DIM];   // first-layer features
__device__ float g_agg[(size_t)N_NODES * H_DIM];   // layer pong
__device__ int   g_cnt[N_NODES];
__device__ int   g_rowptr[N_NODES + 1];
__device__ int   g_cursor[N_NODES];
__device__ int   g_esrc[E_MAX];
__device__ int   g_blocksums[NUM_SCAN_BLOCKS];

// ---------------------------------------------------------------------------
// setup
// ---------------------------------------------------------------------------
__global__ void zero_kernel() {
    int i = blockIdx.x * blockDim.x + threadIdx.x;
    if (i < N_NODES) g_cnt[i] = 0;
}

__global__ void count_kernel(const int* __restrict__ src, const int* __restrict__ dst,
                             int E, int vec_ok) {
    int e = (blockIdx.x * blockDim.x + threadIdx.x) * 4;
    if (vec_ok && e + 3 < E) {
        int4 s = *(const int4*)(src + e);
        int4 d = *(const int4*)(dst + e);
        if (s.x != d.x) atomicAdd(&g_cnt[d.x], 1);
        if (s.y != d.y) atomicAdd(&g_cnt[d.y], 1);
        if (s.z != d.z) atomicAdd(&g_cnt[d.z], 1);
        if (s.w != d.w) atomicAdd(&g_cnt[d.w], 1);
    } else {
        for (; e < E && e < (blockIdx.x * blockDim.x + threadIdx.x) * 4 + 4; e++) {
            int s = src[e], d = dst[e];
            if (s != d) atomicAdd(&g_cnt[d], 1);
        }
    }
}

__global__ void scan_local_kernel() {
    __shared__ int ssum[256];
    int t = threadIdx.x;
    int base = blockIdx.x * SCAN_ELEMS + t * 4;
    int c[4];
    int s = 0;
#pragma unroll
    for (int j = 0; j < 4; j++) {
        int idx = base + j;
        c[j] = (idx < N_NODES) ? g_cnt[idx] : 0;
        s += c[j];
    }
    ssum[t] = s;
    __syncthreads();
#pragma unroll
    for (int off = 1; off < 256; off <<= 1) {
        int v = (t >= off) ? ssum[t - off] : 0;
        __syncthreads();
        ssum[t] += v;
        __syncthreads();
    }
    int p = ssum[t] - s;
#pragma unroll
    for (int j = 0; j < 4; j++) {
        int idx = base + j;
        if (idx < N_NODES) g_rowptr[idx] = p;
        p += c[j];
    }
    if (t == 0) g_blocksums[blockIdx.x] = ssum[255];
}

__global__ void scan_blocksums_kernel() {
    __shared__ int sb[256];
    int t = threadIdx.x;
    int own = (t < NUM_SCAN_BLOCKS) ? g_blocksums[t] : 0;
    sb[t] = own;
    __syncthreads();
#pragma unroll
    for (int off = 1; off < 256; off <<= 1) {
        int v = (t >= off) ? sb[t - off] : 0;
        __syncthreads();
        sb[t] += v;
        __syncthreads();
    }
    if (t < NUM_SCAN_BLOCKS) g_blocksums[t] = sb[t] - own;
    if (t == 0) g_rowptr[N_NODES] = sb[255];
}

__global__ void scan_add_kernel() {
    int i = blockIdx.x * blockDim.x + threadIdx.x;
    if (i >= N_NODES) return;
    int r = g_rowptr[i] + g_blocksums[i / SCAN_ELEMS];
    g_rowptr[i] = r;
    g_cursor[i] = r;
}

__global__ void csr_fill_kernel(const int* __restrict__ src, const int* __restrict__ dst,
                                int E, int vec_ok) {
    int e = (blockIdx.x * blockDim.x + threadIdx.x) * 4;
    if (vec_ok && e + 3 < E) {
        int4 s = *(const int4*)(src + e);
        int4 d = *(const int4*)(dst + e);
        if (s.x != d.x) { int p = atomicAdd(&g_cursor[d.x], 1); if (p < E_MAX) g_esrc[p] = s.x; }
        if (s.y != d.y) { int p = atomicAdd(&g_cursor[d.y], 1); if (p < E_MAX) g_esrc[p] = s.y; }
        if (s.z != d.z) { int p = atomicAdd(&g_cursor[d.z], 1); if (p < E_MAX) g_esrc[p] = s.z; }
        if (s.w != d.w) { int p = atomicAdd(&g_cursor[d.w], 1); if (p < E_MAX) g_esrc[p] = s.w; }
    } else {
        for (; e < E && e < (blockIdx.x * blockDim.x + threadIdx.x) * 4 + 4; e++) {
            int s = src[e], d = dst[e];
            if (s != d) { int p = atomicAdd(&g_cursor[d], 1); if (p < E_MAX) g_esrc[p] = s; }
        }
    }
}

// ---------------------------------------------------------------------------
// gemm1: h = relu(x @ W1 + b1); x_first = h.  4 nodes/warp (proven R5 form).
// ---------------------------------------------------------------------------
__global__ void gemm1_kernel(const float* __restrict__ x,
                             const float* __restrict__ W1,
                             const float* __restrict__ b1) {
    __shared__ float2 Wp[F_IN][32];
    __shared__ float2 bp[32];
    int tid = threadIdx.x;
    for (int i = tid; i < F_IN * 32; i += blockDim.x) {
        int k = i >> 5, c = i & 31;
        Wp[k][c] = make_float2(W1[k * H_DIM + 2 * c], W1[k * H_DIM + 2 * c + 1]);
    }
    if (tid < 32) bp[tid] = make_float2(b1[2 * tid], b1[2 * tid + 1]);
    __syncthreads();

    int lane = tid & 31;
    int warp = (blockIdx.x * blockDim.x + tid) >> 5;
    int nwarps = (gridDim.x * blockDim.x) >> 5;
    const int NG = N_NODES / 4;

    for (int g = warp; g < NG; g += nwarps) {
        int n0 = 4 * g;
        float4 xr[4];
#pragma unroll
        for (int j = 0; j < 4; j++)
            xr[j] = *(const float4*)(x + (size_t)(n0 + j) * F_IN + lane * 4);
        float o0[4] = {0.f, 0.f, 0.f, 0.f}, o1[4] = {0.f, 0.f, 0.f, 0.f};
#pragma unroll
        for (int k = 0; k < F_IN; k++) {
            float2 w = Wp[k][lane];
#pragma unroll
            for (int j = 0; j < 4; j++) {
                float mine = ((k & 3) == 0) ? xr[j].x : ((k & 3) == 1) ? xr[j].y
                           : ((k & 3) == 2) ? xr[j].z : xr[j].w;
                float xv = __shfl_sync(0xffffffffu, mine, k >> 2);
                o0[j] = fmaf(xv, w.x, o0[j]);
                o1[j] = fmaf(xv, w.y, o1[j]);
            }
        }
        float2 b = bp[lane];
#pragma unroll
        for (int j = 0; j < 4; j++) {
            float2 r = make_float2(fmaxf(o0[j] + b.x, 0.f), fmaxf(o1[j] + b.y, 0.f));
            size_t base = (size_t)(n0 + j) * H_DIM + 2 * lane;
            *(float2*)(g_h  + base) = r;
            *(float2*)(g_x1 + base) = r;
        }
    }
}

// ---------------------------------------------------------------------------
// layer kernel: fused [gather + degree-bucket conv (+ output proj/log_softmax)].
// 4 consecutive nodes per warp. Degree derived from rowptr (no sort needed:
// deg distribution is Poisson(16) -> 99.96% of nodes clamp to bucket 5, so
// natural-order groups are same-degree almost surely; rare mixed groups take
// the per-node path).
// Ping-pong: layer 0 reads g_h -> writes g_agg; layer 1 reads g_agg, and
// (LAST) emits log_softmax(h @ Wout + bout) directly, no h store.
// ---------------------------------------------------------------------------
template <bool LAST>
__global__ void layer_kernel(const float* __restrict__ relW,
                             const float* __restrict__ relb,
                             const float* __restrict__ fuse,
                             const float* __restrict__ Wout,
                             const float* __restrict__ bout,
                             float* __restrict__ outbuf,
                             int layer) {
    extern __shared__ unsigned char dyn[];
    float2* Wp  = (float2*)dyn;                       // [NBUCKET][H_DIM][32]
    float2* bpc = Wp + NBUCKET * H_DIM * 32;          // [NBUCKET][32]
    float2* Wo  = bpc + NBUCKET * 32;                 // [H_DIM][20]  (LAST only)
    float2* bo  = Wo + (LAST ? H_DIM * (C_OUT / 2) : 0);

    const float* W = relW + (size_t)layer * NBUCKET * H_DIM * H_DIM;
    const float* B = relb + (size_t)layer * NBUCKET * H_DIM;
    const float* hin = layer ? g_agg : g_h;
    float* hout      = layer ? g_h   : g_agg;

    int tid = threadIdx.x;
    for (int i = tid; i < NBUCKET * H_DIM * 32; i += blockDim.x) {
        int k = i / (H_DIM * 32);
        int r = i - k * (H_DIM * 32);
        int d = r >> 5, c = r & 31;
        const float* Wk = W + ((size_t)k * H_DIM + d) * H_DIM;
        Wp[i] = make_float2(Wk[2 * c], Wk[2 * c + 1]);
    }
    for (int i = tid; i < NBUCKET * 32; i += blockDim.x) {
        int k = i >> 5, c = i & 31;
        bpc[i] = make_float2(B[k * H_DIM + 2 * c], B[k * H_DIM + 2 * c + 1]);
    }
    if (LAST) {
        for (int i = tid; i < H_DIM * (C_OUT / 2); i += blockDim.x) {
            int d = i / (C_OUT / 2), c = i - d * (C_OUT / 2);
            Wo[i] = make_float2(Wout[d * C_OUT + 2 * c], Wout[d * C_OUT + 2 * c + 1]);
        }
        if (tid < C_OUT / 2) bo[tid] = make_float2(bout[2 * tid], bout[2 * tid + 1]);
    }
    __syncthreads();

    float fu = fuse[layer];
    int lane = tid & 31;
    int warp = (blockIdx.x * blockDim.x + tid) >> 5;
    int nwarps = (gridDim.x * blockDim.x) >> 5;
    const int NG = N_NODES / 4;
    size_t col = 2 * (size_t)lane;

    for (int g = warp; g < NG; g += nwarps) {
        int n0 = 4 * g;
        int dgs[4];
        float2 a[4];
        // --- fused gather: agg = self + sum of CSR-row neighbors ---
#pragma unroll
        for (int j = 0; j < 4; j++) {
            int n = n0 + j;
            int rs = g_rowptr[n], re = g_rowptr[n + 1];
            int len = re - rs;
            dgs[j] = len > MAXDEG ? MAXDEG : len;
            float2 acc = *(const float2*)(hin + (size_t)n * H_DIM + col);
            int e = rs;
            for (; e + 4 <= re; e += 4) {
                int s0 = __ldg(g_esrc + e + 0);
                int s1 = __ldg(g_esrc + e + 1);
                int s2 = __ldg(g_esrc + e + 2);
                int s3 = __ldg(g_esrc + e + 3);
                float2 v0 = *(const float2*)(hin + (size_t)s0 * H_DIM + col);
                float2 v1 = *(const float2*)(hin + (size_t)s1 * H_DIM + col);
                float2 v2 = *(const float2*)(hin + (size_t)s2 * H_DIM + col);
                float2 v3 = *(const float2*)(hin + (size_t)s3 * H_DIM + col);
                acc.x += (v0.x + v1.x) + (v2.x + v3.x);
                acc.y += (v0.y + v1.y) + (v2.y + v3.y);
            }
            for (; e < re; e++) {
                int s0 = __ldg(g_esrc + e);
                float2 v = *(const float2*)(hin + (size_t)s0 * H_DIM + col);
                acc.x += v.x; acc.y += v.y;
            }
            a[j] = acc;
        }

        bool same = (dgs[0] == dgs[1]) && (dgs[1] == dgs[2]) && (dgs[2] == dgs[3]);
        float2 hj[4];
        if (same) {
            const float2* Wk = Wp + (size_t)dgs[0] * H_DIM * 32;
            float o0[4] = {0.f, 0.f, 0.f, 0.f}, o1[4] = {0.f, 0.f, 0.f, 0.f};
#pragma unroll
            for (int d = 0; d < H_DIM; d++) {
                float2 w = Wk[d * 32 + lane];
#pragma unroll
                for (int j = 0; j < 4; j++) {
                    float av = __shfl_sync(0xffffffffu, (d & 1) ? a[j].y : a[j].x, d >> 1);
                    o0[j] = fmaf(av, w.x, o0[j]);
                    o1[j] = fmaf(av, w.y, o1[j]);
                }
            }
            float2 b = bpc[dgs[0] * 32 + lane];
#pragma unroll
            for (int j = 0; j < 4; j++) {
                float2 x1 = *(const float2*)(g_x1 + (size_t)(n0 + j) * H_DIM + col);
                hj[j] = make_float2(o0[j] + b.x + fu * x1.x, o1[j] + b.y + fu * x1.y);
            }
        } else {
            for (int j = 0; j < 4; j++) {
                const float2* Wk = Wp + (size_t)dgs[j] * H_DIM * 32;
                float o0 = 0.f, o1 = 0.f;
#pragma unroll
                for (int d = 0; d < H_DIM; d++) {
                    float av = __shfl_sync(0xffffffffu, (d & 1) ? a[j].y : a[j].x, d >> 1);
                    float2 w = Wk[d * 32 + lane];
                    o0 = fmaf(av, w.x, o0);
                    o1 = fmaf(av, w.y, o1);
                }
                float2 b = bpc[dgs[j] * 32 + lane];
                float2 x1 = *(const float2*)(g_x1 + (size_t)(n0 + j) * H_DIM + col);
                hj[j] = make_float2(o0 + b.x + fu * x1.x, o1 + b.y + fu * x1.y);
            }
        }

        if (!LAST) {
#pragma unroll
            for (int j = 0; j < 4; j++)
                *(float2*)(hout + (size_t)(n0 + j) * H_DIM + col) = hj[j];
        } else {
            // fused output projection + log_softmax (hj register-resident)
            bool valid = (lane < C_OUT / 2);
            int cw = valid ? lane : 0;
            float p0[4] = {0.f, 0.f, 0.f, 0.f}, p1[4] = {0.f, 0.f, 0.f, 0.f};
#pragma unroll
            for (int d = 0; d < H_DIM; d++) {
                float2 w = Wo[d * (C_OUT / 2) + cw];
#pragma unroll
                for (int j = 0; j < 4; j++) {
                    float hv = __shfl_sync(0xffffffffu, (d & 1) ? hj[j].y : hj[j].x, d >> 1);
                    p0[j] = fmaf(hv, w.x, p0[j]);
                    p1[j] = fmaf(hv, w.y, p1[j]);
                }
            }
            float2 b2 = bo[cw];
#pragma unroll
            for (int j = 0; j < 4; j++) {
                float a0 = p0[j] + b2.x, a1 = p1[j] + b2.y;
                float m = valid ? fmaxf(a0, a1) : -3.4e38f;
#pragma unroll
                for (int off = 16; off; off >>= 1)
                    m = fmaxf(m, __shfl_xor_sync(0xffffffffu, m, off));
                float s = valid ? (expf(a0 - m) + expf(a1 - m)) : 0.f;
#pragma unroll
                for (int off = 16; off; off >>= 1)
                    s += __shfl_xor_sync(0xffffffffu, s, off);
                float lse = logf(s);
                if (valid)
                    *(float2*)(outbuf + (size_t)(n0 + j) * C_OUT + 2 * lane) =
                        make_float2(a0 - m - lse, a1 - m - lse);
            }
        }
    }
}

// ---------------------------------------------------------------------------
// launch
// ---------------------------------------------------------------------------
extern "C" void kernel_launch(void* const* d_in, const int* in_sizes, int n_in,
                              void* d_out, int out_size) {
    const float* x    = (const float*)d_in[0];
    const int*   edge = (const int*)  d_in[1];
    const float* W1   = (const float*)d_in[2];
    const float* b1   = (const float*)d_in[3];
    const float* relW = (const float*)d_in[4];
    const float* relb = (const float*)d_in[5];
    const float* Wout = (const float*)d_in[6];
    const float* bout = (const float*)d_in[7];
    const float* fuse = (const float*)d_in[8];
    float*       out  = (float*)d_out;
    int E = in_sizes[1] / 2;
    const int* srcp = edge;
    const int* dstp = edge + E;
    int vec_ok = ((E & 3) == 0) ? 1 : 0;

    const int conv_base = (NBUCKET * H_DIM * 32 + NBUCKET * 32) * (int)sizeof(float2); // 99,840
    const int last_extra = (H_DIM * (C_OUT / 2) + C_OUT / 2) * (int)sizeof(float2);    // 10,400
    const int smem0 = conv_base;
    const int smem1 = conv_base + last_extra;                                          // 110,240
    cudaFuncSetAttribute(layer_kernel<false>, cudaFuncAttributeMaxDynamicSharedMemorySize, smem0);
    cudaFuncSetAttribute(layer_kernel<true>,  cudaFuncAttributeMaxDynamicSharedMemorySize, smem1);

    // ---- fork: gemm1 (depends only on x,W1,b1) overlaps CSR setup ----
    cudaStream_t s1 = 0;
    cudaEvent_t evA = 0, evB = 0;
    cudaStreamCreateWithFlags(&s1, cudaStreamNonBlocking);
    cudaEventCreateWithFlags(&evA, cudaEventDisableTiming);
    cudaEventCreateWithFlags(&evB, cudaEventDisableTiming);

    cudaEventRecord(evA, (cudaStream_t)0);
    cudaStreamWaitEvent(s1, evA, 0);
    gemm1_kernel<<<592, 256, 0, s1>>>(x, W1, b1);
    cudaEventRecord(evB, s1);

    // ---- setup on main stream ----
    zero_kernel<<<(N_NODES + 255) / 256, 256>>>();
    count_kernel<<<((E + 3) / 4 + 255) / 256, 256>>>(srcp, dstp, E, vec_ok);
    scan_local_kernel<<<NUM_SCAN_BLOCKS, 256>>>();
    scan_blocksums_kernel<<<1, 256>>>();
    scan_add_kernel<<<(N_NODES + 255) / 256, 256>>>();
    csr_fill_kernel<<<((E + 3) / 4 + 255) / 256, 256>>>(srcp, dstp, E, vec_ok);

    // ---- join, then fused layers ----
    cudaStreamWaitEvent((cudaStream_t)0, evB, 0);
    layer_kernel<false><<<296, 512, smem0>>>(relW, relb, fuse, Wout, bout, out, 0);
    layer_kernel<true> <<<296, 512, smem1>>>(relW, relb, fuse, Wout, bout, out, 1);
    // s1/evA/evB intentionally not destroyed: kernel_launch runs only a few
    // times (correctness + capture); destroying mid-capture is illegal and no
    // device memory is involved.
}

// round 10
// speedup vs baseline: 1.5837x; 1.5837x over previous
#include <cuda_runtime.h>
#include <cstdint>

#define N_NODES 200000
#define F_IN    128
#define H_DIM   64
#define C_OUT   40
#define MAXDEG  5
#define NBUCKET 6
#define NUM_LAYERS 2
#define E_MAX   3400000

#define SCAN_ELEMS 1024
#define NUM_SCAN_BLOCKS ((N_NODES + SCAN_ELEMS - 1) / SCAN_ELEMS)   // 196

// ---------------- scratch (__device__ globals: allocation-free rule) --------
__device__ float g_h  [(size_t)N_NODES * H_DIM];
__device__ float g_x1 [(size_t)N_NODES * H_DIM];
__device__ float g_agg[(size_t)N_NODES * H_DIM];
__device__ int   g_cnt[N_NODES];
__device__ int   g_rowptr[N_NODES + 1];
__device__ int   g_cursor[N_NODES];
__device__ int   g_esrc[E_MAX];
__device__ int   g_blocksums[NUM_SCAN_BLOCKS];

// ---------------------------------------------------------------------------
// setup
// ---------------------------------------------------------------------------
__global__ void zero_kernel() {
    int i = blockIdx.x * blockDim.x + threadIdx.x;
    if (i < N_NODES) g_cnt[i] = 0;
}

__global__ void count_kernel(const int* __restrict__ src, const int* __restrict__ dst,
                             int E, int vec_ok) {
    int e = (blockIdx.x * blockDim.x + threadIdx.x) * 4;
    if (vec_ok && e + 3 < E) {
        int4 s = *(const int4*)(src + e);
        int4 d = *(const int4*)(dst + e);
        if (s.x != d.x) atomicAdd(&g_cnt[d.x], 1);
        if (s.y != d.y) atomicAdd(&g_cnt[d.y], 1);
        if (s.z != d.z) atomicAdd(&g_cnt[d.z], 1);
        if (s.w != d.w) atomicAdd(&g_cnt[d.w], 1);
    } else {
        for (; e < E && e < (blockIdx.x * blockDim.x + threadIdx.x) * 4 + 4; e++) {
            int s = src[e], d = dst[e];
            if (s != d) atomicAdd(&g_cnt[d], 1);
        }
    }
}

__global__ void scan_local_kernel() {
    __shared__ int ssum[256];
    int t = threadIdx.x;
    int base = blockIdx.x * SCAN_ELEMS + t * 4;
    int c[4];
    int s = 0;
#pragma unroll
    for (int j = 0; j < 4; j++) {
        int idx = base + j;
        c[j] = (idx < N_NODES) ? g_cnt[idx] : 0;
        s += c[j];
    }
    ssum[t] = s;
    __syncthreads();
#pragma unroll
    for (int off = 1; off < 256; off <<= 1) {
        int v = (t >= off) ? ssum[t - off] : 0;
        __syncthreads();
        ssum[t] += v;
        __syncthreads();
    }
    int p = ssum[t] - s;
#pragma unroll
    for (int j = 0; j < 4; j++) {
        int idx = base + j;
        if (idx < N_NODES) g_rowptr[idx] = p;
        p += c[j];
    }
    if (t == 0) g_blocksums[blockIdx.x] = ssum[255];
}

__global__ void scan_blocksums_kernel() {
    __shared__ int sb[256];
    int t = threadIdx.x;
    int own = (t < NUM_SCAN_BLOCKS) ? g_blocksums[t] : 0;
    sb[t] = own;
    __syncthreads();
#pragma unroll
    for (int off = 1; off < 256; off <<= 1) {
        int v = (t >= off) ? sb[t - off] : 0;
        __syncthreads();
        sb[t] += v;
        __syncthreads();
    }
    if (t < NUM_SCAN_BLOCKS) g_blocksums[t] = sb[t] - own;
    if (t == 0) g_rowptr[N_NODES] = sb[255];
}

__global__ void scan_add_kernel() {
    int i = blockIdx.x * blockDim.x + threadIdx.x;
    if (i >= N_NODES) return;
    int r = g_rowptr[i] + g_blocksums[i / SCAN_ELEMS];
    g_rowptr[i] = r;
    g_cursor[i] = r;
}

__global__ void csr_fill_kernel(const int* __restrict__ src, const int* __restrict__ dst,
                                int E, int vec_ok) {
    int e = (blockIdx.x * blockDim.x + threadIdx.x) * 4;
    if (vec_ok && e + 3 < E) {
        int4 s = *(const int4*)(src + e);
        int4 d = *(const int4*)(dst + e);
        if (s.x != d.x) { int p = atomicAdd(&g_cursor[d.x], 1); if (p < E_MAX) g_esrc[p] = s.x; }
        if (s.y != d.y) { int p = atomicAdd(&g_cursor[d.y], 1); if (p < E_MAX) g_esrc[p] = s.y; }
        if (s.z != d.z) { int p = atomicAdd(&g_cursor[d.z], 1); if (p < E_MAX) g_esrc[p] = s.z; }
        if (s.w != d.w) { int p = atomicAdd(&g_cursor[d.w], 1); if (p < E_MAX) g_esrc[p] = s.w; }
    } else {
        for (; e < E && e < (blockIdx.x * blockDim.x + threadIdx.x) * 4 + 4; e++) {
            int s = src[e], d = dst[e];
            if (s != d) { int p = atomicAdd(&g_cursor[d], 1); if (p < E_MAX) g_esrc[p] = s; }
        }
    }
}

// ---------------------------------------------------------------------------
// gemm1: h = relu(x @ W1 + b1); x_first = h.  4 nodes/warp (R5 proven form).
// ---------------------------------------------------------------------------
__global__ void gemm1_kernel(const float* __restrict__ x,
                             const float* __restrict__ W1,
                             const float* __restrict__ b1) {
    __shared__ float2 Wp[F_IN][32];
    __shared__ float2 bp[32];
    int tid = threadIdx.x;
    for (int i = tid; i < F_IN * 32; i += blockDim.x) {
        int k = i >> 5, c = i & 31;
        Wp[k][c] = make_float2(W1[k * H_DIM + 2 * c], W1[k * H_DIM + 2 * c + 1]);
    }
    if (tid < 32) bp[tid] = make_float2(b1[2 * tid], b1[2 * tid + 1]);
    __syncthreads();

    int lane = tid & 31;
    int warp = (blockIdx.x * blockDim.x + tid) >> 5;
    int nwarps = (gridDim.x * blockDim.x) >> 5;
    const int NG = N_NODES / 4;

    for (int g = warp; g < NG; g += nwarps) {
        int n0 = 4 * g;
        float4 xr[4];
#pragma unroll
        for (int j = 0; j < 4; j++)
            xr[j] = *(const float4*)(x + (size_t)(n0 + j) * F_IN + lane * 4);
        float o0[4] = {0.f, 0.f, 0.f, 0.f}, o1[4] = {0.f, 0.f, 0.f, 0.f};
#pragma unroll
        for (int k = 0; k < F_IN; k++) {
            float2 w = Wp[k][lane];
#pragma unroll
            for (int j = 0; j < 4; j++) {
                float mine = ((k & 3) == 0) ? xr[j].x : ((k & 3) == 1) ? xr[j].y
                           : ((k & 3) == 2) ? xr[j].z : xr[j].w;
                float xv = __shfl_sync(0xffffffffu, mine, k >> 2);
                o0[j] = fmaf(xv, w.x, o0[j]);
                o1[j] = fmaf(xv, w.y, o1[j]);
            }
        }
        float2 b = bp[lane];
#pragma unroll
        for (int j = 0; j < 4; j++) {
            float2 r = make_float2(fmaxf(o0[j] + b.x, 0.f), fmaxf(o1[j] + b.y, 0.f));
            size_t base = (size_t)(n0 + j) * H_DIM + 2 * lane;
            *(float2*)(g_h  + base) = r;
            *(float2*)(g_x1 + base) = r;
        }
    }
}

// ---------------------------------------------------------------------------
// agg: agg[n] = h[n] + sum CSR row.  Warp per node, zero smem, full occupancy
// (this high-occupancy standalone form is the R5 winner — do not fuse).
// ---------------------------------------------------------------------------
__global__ void agg_kernel() {
    int lane = threadIdx.x & 31;
    int node = (blockIdx.x * blockDim.x + threadIdx.x) >> 5;
    if (node >= N_NODES) return;
    int rs = g_rowptr[node], re = g_rowptr[node + 1];
    size_t col = 2 * lane;
    float2 acc = *(const float2*)(g_h + (size_t)node * H_DIM + col);
    int e = rs;
    for (; e + 4 <= re; e += 4) {
        int s0 = __ldg(g_esrc + e + 0);
        int s1 = __ldg(g_esrc + e + 1);
        int s2 = __ldg(g_esrc + e + 2);
        int s3 = __ldg(g_esrc + e + 3);
        float2 v0 = *(const float2*)(g_h + (size_t)s0 * H_DIM + col);
        float2 v1 = *(const float2*)(g_h + (size_t)s1 * H_DIM + col);
        float2 v2 = *(const float2*)(g_h + (size_t)s2 * H_DIM + col);
        float2 v3 = *(const float2*)(g_h + (size_t)s3 * H_DIM + col);
        acc.x += (v0.x + v1.x) + (v2.x + v3.x);
        acc.y += (v0.y + v1.y) + (v2.y + v3.y);
    }
    for (; e < re; e++) {
        int s0 = __ldg(g_esrc + e);
        float2 v = *(const float2*)(g_h + (size_t)s0 * H_DIM + col);
        acc.x += v.x; acc.y += v.y;
    }
    *(float2*)(g_agg + (size_t)node * H_DIM + col) = acc;
}

// ---------------------------------------------------------------------------
// conv: h = agg @ relW[l][deg] + relb[l][deg] + fuse*x_first.
// 4 consecutive nodes/warp; degree from rowptr diffs (no sort: raw degree is
// ~Poisson(16) so ~99.99% of nodes clamp to bucket 5 — natural groups are
// uniform almost surely; rare mixed groups take the per-node path).
// ---------------------------------------------------------------------------
__global__ void conv_kernel(const float* __restrict__ relW,
                            const float* __restrict__ relb,
                            const float* __restrict__ fuse,
                            int layer) {
    extern __shared__ float2 sm[];
    float2* Wp = sm;                            // [NBUCKET][H_DIM][32]
    float2* bp = sm + NBUCKET * H_DIM * 32;     // [NBUCKET][32]

    const float* W = relW + (size_t)layer * NBUCKET * H_DIM * H_DIM;
    const float* B = relb + (size_t)layer * NBUCKET * H_DIM;

    int tid = threadIdx.x;
    for (int i = tid; i < NBUCKET * H_DIM * 32; i += blockDim.x) {
        int k = i / (H_DIM * 32);
        int r = i - k * (H_DIM * 32);
        int d = r >> 5, c = r & 31;
        const float* Wk = W + ((size_t)k * H_DIM + d) * H_DIM;
        Wp[i] = make_float2(Wk[2 * c], Wk[2 * c + 1]);
    }
    for (int i = tid; i < NBUCKET * 32; i += blockDim.x) {
        int k = i >> 5, c = i & 31;
        bp[i] = make_float2(B[k * H_DIM + 2 * c], B[k * H_DIM + 2 * c + 1]);
    }
    __syncthreads();

    float fu = fuse[layer];
    int lane = tid & 31;
    int warp = (blockIdx.x * blockDim.x + tid) >> 5;
    int nwarps = (gridDim.x * blockDim.x) >> 5;
    const int NG = N_NODES / 4;

    for (int g = warp; g < NG; g += nwarps) {
        int n0 = 4 * g;
        int dg[4];
#pragma unroll
        for (int j = 0; j < 4; j++) {
            int len = g_rowptr[n0 + j + 1] - g_rowptr[n0 + j];
            dg[j] = len > MAXDEG ? MAXDEG : len;
        }
        if (dg[0] == dg[1] && dg[1] == dg[2] && dg[2] == dg[3]) {
            // fast path: shared weight bucket
            const float2* Wk = Wp + (size_t)dg[0] * H_DIM * 32;
            float2 a[4];
#pragma unroll
            for (int j = 0; j < 4; j++)
                a[j] = *(const float2*)(g_agg + (size_t)(n0 + j) * H_DIM + 2 * lane);
            float o0[4] = {0.f, 0.f, 0.f, 0.f}, o1[4] = {0.f, 0.f, 0.f, 0.f};
#pragma unroll
            for (int d = 0; d < H_DIM; d++) {
                float2 w = Wk[d * 32 + lane];
#pragma unroll
                for (int j = 0; j < 4; j++) {
                    float av = __shfl_sync(0xffffffffu, (d & 1) ? a[j].y : a[j].x, d >> 1);
                    o0[j] = fmaf(av, w.x, o0[j]);
                    o1[j] = fmaf(av, w.y, o1[j]);
                }
            }
            float2 b = bp[dg[0] * 32 + lane];
#pragma unroll
            for (int j = 0; j < 4; j++) {
                size_t base = (size_t)(n0 + j) * H_DIM + 2 * lane;
                float2 x1 = *(const float2*)(g_x1 + base);
                *(float2*)(g_h + base) =
                    make_float2(o0[j] + b.x + fu * x1.x, o1[j] + b.y + fu * x1.y);
            }
        } else {
            // mixed-degree group (rare): per-node path
            for (int j = 0; j < 4; j++) {
                const float2* Wk = Wp + (size_t)dg[j] * H_DIM * 32;
                float2 a = *(const float2*)(g_agg + (size_t)(n0 + j) * H_DIM + 2 * lane);
                float o0 = 0.f, o1 = 0.f;
#pragma unroll
                for (int d = 0; d < H_DIM; d++) {
                    float av = __shfl_sync(0xffffffffu, (d & 1) ? a.y : a.x, d >> 1);
                    float2 w = Wk[d * 32 + lane];
                    o0 = fmaf(av, w.x, o0);
                    o1 = fmaf(av, w.y, o1);
                }
                float2 b = bp[dg[j] * 32 + lane];
                size_t base = (size_t)(n0 + j) * H_DIM + 2 * lane;
                float2 x1 = *(const float2*)(g_x1 + base);
                *(float2*)(g_h + base) =
                    make_float2(o0 + b.x + fu * x1.x, o1 + b.y + fu * x1.y);
            }
        }
    }
}

// ---------------------------------------------------------------------------
// out = log_softmax(h @ Wout + bout). 4 nodes/warp (R5 proven form).
// ---------------------------------------------------------------------------
__global__ void out_kernel(const float* __restrict__ Wout,
                           const float* __restrict__ bout,
                           float* __restrict__ out) {
    __shared__ float2 Wp[H_DIM][32];
    __shared__ float2 bp[32];
    int tid = threadIdx.x;
    for (int i = tid; i < H_DIM * 32; i += blockDim.x) {
        int d = i >> 5, c = i & 31;
        Wp[d][c] = (c < C_OUT / 2)
            ? make_float2(Wout[d * C_OUT + 2 * c], Wout[d * C_OUT + 2 * c + 1])
            : make_float2(0.f, 0.f);
    }
    if (tid < 32)
        bp[tid] = (tid < C_OUT / 2) ? make_float2(bout[2 * tid], bout[2 * tid + 1])
                                    : make_float2(0.f, 0.f);
    __syncthreads();

    int lane = tid & 31;
    int warp = (blockIdx.x * blockDim.x + tid) >> 5;
    int nwarps = (gridDim.x * blockDim.x) >> 5;
    const int NG = N_NODES / 4;

    for (int g = warp; g < NG; g += nwarps) {
        int n0 = 4 * g;
        float2 hr[4];
#pragma unroll
        for (int j = 0; j < 4; j++)
            hr[j] = *(const float2*)(g_h + (size_t)(n0 + j) * H_DIM + 2 * lane);
        float o0[4] = {0.f, 0.f, 0.f, 0.f}, o1[4] = {0.f, 0.f, 0.f, 0.f};
#pragma unroll
        for (int d = 0; d < H_DIM; d++) {
            float2 w = Wp[d][lane];
#pragma unroll
            for (int j = 0; j < 4; j++) {
                float hv = __shfl_sync(0xffffffffu, (d & 1) ? hr[j].y : hr[j].x, d >> 1);
                o0[j] = fmaf(hv, w.x, o0[j]);
                o1[j] = fmaf(hv, w.y, o1[j]);
            }
        }
        float2 b = bp[lane];
        bool valid = (lane < C_OUT / 2);
#pragma unroll
        for (int j = 0; j < 4; j++) {
            float a0 = o0[j] + b.x, a1 = o1[j] + b.y;
            float m = valid ? fmaxf(a0, a1) : -3.4e38f;
#pragma unroll
            for (int off = 16; off; off >>= 1)
                m = fmaxf(m, __shfl_xor_sync(0xffffffffu, m, off));
            float s = valid ? (expf(a0 - m) + expf(a1 - m)) : 0.f;
#pragma unroll
            for (int off = 16; off; off >>= 1)
                s += __shfl_xor_sync(0xffffffffu, s, off);
            float lse = logf(s);
            if (valid)
                *(float2*)(out + (size_t)(n0 + j) * C_OUT + 2 * lane) =
                    make_float2(a0 - m - lse, a1 - m - lse);
        }
    }
}

// ---------------------------------------------------------------------------
// launch
// ---------------------------------------------------------------------------
extern "C" void kernel_launch(void* const* d_in, const int* in_sizes, int n_in,
                              void* d_out, int out_size) {
    const float* x    = (const float*)d_in[0];
    const int*   edge = (const int*)  d_in[1];
    const float* W1   = (const float*)d_in[2];
    const float* b1   = (const float*)d_in[3];
    const float* relW = (const float*)d_in[4];
    const float* relb = (const float*)d_in[5];
    const float* Wout = (const float*)d_in[6];
    const float* bout = (const float*)d_in[7];
    const float* fuse = (const float*)d_in[8];
    float*       out  = (float*)d_out;
    int E = in_sizes[1] / 2;
    const int* srcp = edge;
    const int* dstp = edge + E;
    int vec_ok = ((E & 3) == 0) ? 1 : 0;

    const int conv_smem = (NBUCKET * H_DIM * 32 + NBUCKET * 32) * (int)sizeof(float2); // 99,840 B
    cudaFuncSetAttribute(conv_kernel, cudaFuncAttributeMaxDynamicSharedMemorySize, conv_smem);

    // ---- fork: gemm1 (depends only on x,W1,b1) overlaps CSR setup ----
    cudaStream_t s1 = 0;
    cudaEvent_t evA = 0, evB = 0;
    cudaStreamCreateWithFlags(&s1, cudaStreamNonBlocking);
    cudaEventCreateWithFlags(&evA, cudaEventDisableTiming);
    cudaEventCreateWithFlags(&evB, cudaEventDisableTiming);

    cudaEventRecord(evA, (cudaStream_t)0);
    cudaStreamWaitEvent(s1, evA, 0);
    gemm1_kernel<<<592, 256, 0, s1>>>(x, W1, b1);
    cudaEventRecord(evB, s1);

    // ---- setup on main stream: degree counts + CSR (no bucket sort) ----
    zero_kernel<<<(N_NODES + 255) / 256, 256>>>();
    count_kernel<<<((E + 3) / 4 + 255) / 256, 256>>>(srcp, dstp, E, vec_ok);
    scan_local_kernel<<<NUM_SCAN_BLOCKS, 256>>>();
    scan_blocksums_kernel<<<1, 256>>>();
    scan_add_kernel<<<(N_NODES + 255) / 256, 256>>>();
    csr_fill_kernel<<<((E + 3) / 4 + 255) / 256, 256>>>(srcp, dstp, E, vec_ok);

    // ---- join, then network (R5 structure) ----
    cudaStreamWaitEvent((cudaStream_t)0, evB, 0);
    for (int l = 0; l < NUM_LAYERS; l++) {
        agg_kernel<<<(N_NODES * 32 + 255) / 256, 256>>>();
        conv_kernel<<<296, 512, conv_smem>>>(relW, relb, fuse, l);
    }
    out_kernel<<<592, 256>>>(Wout, bout, out);
    // s1/evA/evB intentionally not destroyed: kernel_launch runs only a few
    // times (correctness + capture); destroying mid-capture is illegal and no
    // device memory is involved.
}